// round 9
// baseline (speedup 1.0000x reference)
#include <cuda_runtime.h>

// Per-node weight accumulator. Zero at module load; the fused kernel re-zeroes
// it after consuming, so every graph replay starts from zeros.
__device__ __align__(16) float g_w[4 * 1024 * 1024];
__device__ double g_acc[8];
__device__ unsigned int g_bar;    // phase barrier counter (reset each replay)
__device__ unsigned int g_count;  // finalize counter (wraps via atomicInc)

static const int THREADS = 256;
static const int BLOCKS  = 592;   // 148 SMs x 4 CTAs -> all co-resident

__global__ __launch_bounds__(THREADS, 4) void fused_kernel(
    const float*  __restrict__ coords,    // (N_NODES, 2)
    const int*    __restrict__ elements,  // (E, 3)
    const float4* __restrict__ vals4,     // 2*N_NODES float4s
    float* __restrict__ out,
    int n_elements, int n_f4)
{
    const int T = BLOCKS * THREADS;  // 151,552 (even)
    const int t = blockIdx.x * THREADS + threadIdx.x;

    // ---------------- Phase 1: det(J) scattered to node weights -------------
    for (int e = t; e < n_elements; e += T) {
        const int i0 = __ldcs(elements + 3 * e + 0);
        const int i1 = __ldcs(elements + 3 * e + 1);
        const int i2 = __ldcs(elements + 3 * e + 2);

        const float2 c0 = *reinterpret_cast<const float2*>(coords + 2 * i0);
        const float2 c1 = *reinterpret_cast<const float2*>(coords + 2 * i1);
        const float2 c2 = *reinterpret_cast<const float2*>(coords + 2 * i2);

        // det(J) for Tri3; quad weight 1/6 folded into finalize.
        const float det = (c1.x - c0.x) * (c2.y - c0.y)
                        - (c1.y - c0.y) * (c2.x - c0.x);

        atomicAdd(&g_w[i0], det);   // REDG.F32, no return
        atomicAdd(&g_w[i1], det);
        atomicAdd(&g_w[i2], det);
    }

    // ---------------- Device-wide barrier (all blocks co-resident) ----------
    __threadfence();   // make REDG results visible before signaling
    __syncthreads();
    if (threadIdx.x == 0) {
        atomicAdd(&g_bar, 1u);
        while (*(volatile unsigned int*)&g_bar < (unsigned int)BLOCKS)
            __nanosleep(64);
    }
    __syncthreads();
    __threadfence();   // acquire: see all g_w updates

    // ---------------- Phase 2: out[v] = (1/6) sum_n w[n]*vals[n][v] ---------
    // Parity scheme: even float4 j -> v0..3 of node j/2, odd j -> v4..7.
    // T is even, so thread parity == j parity for all its loads.
    float4 acc = make_float4(0.f, 0.f, 0.f, 0.f);
    const bool even = ((t & 1) == 0);

    for (int j0 = t; j0 < n_f4; j0 += 4 * T) {
        float  wreg[4];
        float4 vreg[4];
#pragma unroll
        for (int k = 0; k < 4; k++) {
            const int j = j0 + k * T;
            if (j < n_f4) {
                wreg[k] = g_w[j >> 1];
                vreg[k] = vals4[j];
            } else {
                wreg[k] = 0.0f;
                vreg[k] = make_float4(0.f, 0.f, 0.f, 0.f);
            }
        }
        if (even) {  // even thread owns even j = 2n -> zeroes every node once
#pragma unroll
            for (int k = 0; k < 4; k++) {
                const int j = j0 + k * T;
                if (j < n_f4) g_w[j >> 1] = 0.0f;
            }
        }
#pragma unroll
        for (int k = 0; k < 4; k++) {
            acc.x += wreg[k] * vreg[k].x;
            acc.y += wreg[k] * vreg[k].y;
            acc.z += wreg[k] * vreg[k].z;
            acc.w += wreg[k] * vreg[k].w;
        }
    }

    // Parity-preserving xor reduction (16,8,4,2): lane0 = even-lane sum
    // (v0-3), lane1 = odd-lane sum (v4-7).
#pragma unroll
    for (int off = 16; off >= 2; off >>= 1) {
        acc.x += __shfl_xor_sync(0xFFFFFFFFu, acc.x, off);
        acc.y += __shfl_xor_sync(0xFFFFFFFFu, acc.y, off);
        acc.z += __shfl_xor_sync(0xFFFFFFFFu, acc.z, off);
        acc.w += __shfl_xor_sync(0xFFFFFFFFu, acc.w, off);
    }

    __shared__ float4 sred[8][2];  // [warp][parity]
    const int warp = threadIdx.x >> 5;
    const int lane = threadIdx.x & 31;
    if (lane < 2) sred[warp][lane] = acc;
    __syncthreads();

    if (threadIdx.x < 2) {
        const int p = threadIdx.x;  // 0 -> v0-3, 1 -> v4-7
        float4 sum = make_float4(0.f, 0.f, 0.f, 0.f);
#pragma unroll
        for (int w = 0; w < 8; w++) {
            sum.x += sred[w][p].x;  sum.y += sred[w][p].y;
            sum.z += sred[w][p].z;  sum.w += sred[w][p].w;
        }
        atomicAdd(&g_acc[4 * p + 0], (double)sum.x);
        atomicAdd(&g_acc[4 * p + 1], (double)sum.y);
        atomicAdd(&g_acc[4 * p + 2], (double)sum.z);
        atomicAdd(&g_acc[4 * p + 3], (double)sum.w);
    }

    // Last-block-done: finalize + reset all replay state.
    __shared__ bool is_last;
    __threadfence();
    if (threadIdx.x == 0) {
        unsigned int old = atomicInc(&g_count, (unsigned int)(BLOCKS - 1));
        is_last = (old == (unsigned int)(BLOCKS - 1));
    }
    __syncthreads();

    if (is_last) {
        if (threadIdx.x < 8) {
            const double val = atomicAdd(&g_acc[threadIdx.x], 0.0);
            out[threadIdx.x] = (float)(val * (1.0 / 6.0));  // fold quad weight
            g_acc[threadIdx.x] = 0.0;
        }
        __syncthreads();
        if (threadIdx.x == 0) g_bar = 0u;  // safe: all blocks passed the spin
    }
}

extern "C" void kernel_launch(void* const* d_in, const int* in_sizes, int n_in,
                              void* d_out, int out_size) {
    const float* nodal_values = (const float*)d_in[0];
    const float* coords       = (const float*)d_in[1];
    const int*   elements     = (const int*)d_in[2];
    float* out = (float*)d_out;

    const int n_elements = in_sizes[2] / 3;
    const int n_nodes    = in_sizes[1] / 2;
    const int n_f4       = n_nodes * 2;

    fused_kernel<<<BLOCKS, THREADS>>>(
        coords, elements, reinterpret_cast<const float4*>(nodal_values),
        out, n_elements, n_f4);
}